// round 2
// baseline (speedup 1.0000x reference)
#include <cuda_runtime.h>
#include <math.h>

#define BB 4
#define TT 2048
#define DM 1024
#define NH 16
#define DH 64
#define M_TOT (BB*TT)   // 8192

// Scratch (allocation-free rule: device globals)
__device__ float g_qkv[(size_t)BB*TT*3*DM];   // [B,T,3D]  ~100.7 MB
__device__ float g_att[(size_t)BB*TT*DM];     // [B,T,D]   ~33.6 MB

// ---------------------------------------------------------------------------
// SGEMM (NT): C[M][N] = sum_k A[M][K][m,k] * B[N][K][n,k]
// BM=BN=128, BK=8, 256 threads, 8x8 per thread. M,N,K all multiples of tile.
// ---------------------------------------------------------------------------
__global__ __launch_bounds__(256) void sgemm_nt(
    const float* __restrict__ A, const float* __restrict__ B,
    float* __restrict__ C, int N, int K)
{
    __shared__ float As[8][128];
    __shared__ float Bs[8][128];
    const int tid = threadIdx.x;
    const float* Ab = A + (size_t)blockIdx.y * 128 * K;
    const float* Bb = B + (size_t)blockIdx.x * 128 * K;
    const int lr = tid >> 1;          // 0..127
    const int lc = (tid & 1) * 4;     // 0 or 4
    const int ty = tid >> 4, tx = tid & 15;

    float acc[8][8];
#pragma unroll
    for (int i = 0; i < 8; i++)
#pragma unroll
        for (int j = 0; j < 8; j++) acc[i][j] = 0.f;

    for (int k0 = 0; k0 < K; k0 += 8) {
        float4 av = *(const float4*)(Ab + (size_t)lr * K + k0 + lc);
        float4 bv = *(const float4*)(Bb + (size_t)lr * K + k0 + lc);
        As[lc+0][lr] = av.x; As[lc+1][lr] = av.y; As[lc+2][lr] = av.z; As[lc+3][lr] = av.w;
        Bs[lc+0][lr] = bv.x; Bs[lc+1][lr] = bv.y; Bs[lc+2][lr] = bv.z; Bs[lc+3][lr] = bv.w;
        __syncthreads();
#pragma unroll
        for (int k = 0; k < 8; k++) {
            float a[8], b[8];
#pragma unroll
            for (int i = 0; i < 8; i++) a[i] = As[k][ty*8 + i];
#pragma unroll
            for (int j = 0; j < 8; j++) b[j] = Bs[k][tx*8 + j];
#pragma unroll
            for (int i = 0; i < 8; i++)
#pragma unroll
                for (int j = 0; j < 8; j++)
                    acc[i][j] = fmaf(a[i], b[j], acc[i][j]);
        }
        __syncthreads();
    }

    float* Cb = C + (size_t)(blockIdx.y*128 + ty*8) * N + blockIdx.x*128 + tx*8;
#pragma unroll
    for (int i = 0; i < 8; i++) {
        *(float4*)(Cb + (size_t)i*N)     = make_float4(acc[i][0], acc[i][1], acc[i][2], acc[i][3]);
        *(float4*)(Cb + (size_t)i*N + 4) = make_float4(acc[i][4], acc[i][5], acc[i][6], acc[i][7]);
    }
}

// ---------------------------------------------------------------------------
// Flash attention, fp32, non-causal. Grid: (T/64, B*H), 256 threads.
// Per block: 64 queries of one (b,h). Loop K/V in 64-row tiles.
// Thread micro-tile: 2 queries (qg = tid>>3) x 8 keys / 8 dims (kg = tid&7).
// Dynamic smem: Qs[64][65] | Ks/Ps union [64][65] | Vs[64][68]  = 50688 B
// ---------------------------------------------------------------------------
extern __shared__ float f_smem[];
#define QS(r,c) f_smem[(r)*65 + (c)]
#define KS(r,c) f_smem[4160 + (r)*65 + (c)]
#define PS(r,c) f_smem[4160 + (r)*65 + (c)]
#define VS(r,c) f_smem[8320 + (r)*68 + (c)]

__global__ __launch_bounds__(256) void flash_attn()
{
    const int tid = threadIdx.x;
    const int qt  = blockIdx.x;          // query tile
    const int bh  = blockIdx.y;
    const int b   = bh >> 4, h = bh & 15;
    const int qg  = tid >> 3;            // 0..31
    const int kg  = tid & 7;             // 0..7
    const int qa  = 2*qg, qb = 2*qg + 1;

    const size_t base = (size_t)b * TT * (3*DM);
    const int qoff = h*DH, koff = DM + h*DH, voff = 2*DM + h*DH;
    const int q0 = qt * 64;

    // Load + pre-scale Q tile
    for (int i = tid; i < 64*64; i += 256) {
        int r = i >> 6, c = i & 63;
        QS(r, c) = g_qkv[base + (size_t)(q0 + r)*(3*DM) + qoff + c] * 0.125f;
    }

    float m0 = -INFINITY, m1 = -INFINITY;
    float l0 = 0.f, l1 = 0.f;
    float a0[8], a1[8];
#pragma unroll
    for (int j = 0; j < 8; j++) { a0[j] = 0.f; a1[j] = 0.f; }

    for (int kt = 0; kt < TT; kt += 64) {
        __syncthreads();  // prior PV done (Ps/Vs free); also orders Q load on iter 0
        for (int i = tid; i < 64*64; i += 256) {
            int r = i >> 6, c = i & 63;
            size_t rb = base + (size_t)(kt + r)*(3*DM);
            KS(r, c) = g_qkv[rb + koff + c];
            VS(r, c) = g_qkv[rb + voff + c];
        }
        __syncthreads();

        // ---- scores: s[q r][kk] for k = kg + 8*kk (conflict-free interleave)
        float s0[8], s1[8];
#pragma unroll
        for (int kk = 0; kk < 8; kk++) { s0[kk] = 0.f; s1[kk] = 0.f; }
#pragma unroll 4
        for (int d = 0; d < 64; d++) {
            float qv0 = QS(qa, d), qv1 = QS(qb, d);
#pragma unroll
            for (int kk = 0; kk < 8; kk++) {
                float kv = KS(kg + 8*kk, d);
                s0[kk] = fmaf(qv0, kv, s0[kk]);
                s1[kk] = fmaf(qv1, kv, s1[kk]);
            }
        }
        __syncthreads();  // Ks reads complete before Ps (aliased) writes

        // ---- online softmax across the 8-lane key group
        float t0 = s0[0], t1 = s1[0];
#pragma unroll
        for (int kk = 1; kk < 8; kk++) { t0 = fmaxf(t0, s0[kk]); t1 = fmaxf(t1, s1[kk]); }
#pragma unroll
        for (int w = 1; w < 8; w <<= 1) {
            t0 = fmaxf(t0, __shfl_xor_sync(0xffffffffu, t0, w));
            t1 = fmaxf(t1, __shfl_xor_sync(0xffffffffu, t1, w));
        }
        float m0n = fmaxf(m0, t0), m1n = fmaxf(m1, t1);
        float c0 = __expf(m0 - m0n), c1 = __expf(m1 - m1n);
        float ls0 = 0.f, ls1 = 0.f;
#pragma unroll
        for (int kk = 0; kk < 8; kk++) {
            float p0 = __expf(s0[kk] - m0n);
            float p1 = __expf(s1[kk] - m1n);
            ls0 += p0; ls1 += p1;
            PS(qa, kg + 8*kk) = p0;
            PS(qb, kg + 8*kk) = p1;
        }
#pragma unroll
        for (int w = 1; w < 8; w <<= 1) {
            ls0 += __shfl_xor_sync(0xffffffffu, ls0, w);
            ls1 += __shfl_xor_sync(0xffffffffu, ls1, w);
        }
        l0 = l0*c0 + ls0;  l1 = l1*c1 + ls1;
        m0 = m0n;          m1 = m1n;
#pragma unroll
        for (int j = 0; j < 8; j++) { a0[j] *= c0; a1[j] *= c1; }
        __syncwarp();  // Ps rows are produced/consumed within one warp

        // ---- PV: thread owns dims d = kg*8 .. kg*8+7 (float4 x2, conflict-free)
#pragma unroll 4
        for (int k = 0; k < 64; k++) {
            float p0 = PS(qa, k), p1 = PS(qb, k);
            float4 v0 = *(const float4*)&VS(k, kg*8);
            float4 v1 = *(const float4*)&VS(k, kg*8 + 4);
            a0[0] = fmaf(p0, v0.x, a0[0]); a0[1] = fmaf(p0, v0.y, a0[1]);
            a0[2] = fmaf(p0, v0.z, a0[2]); a0[3] = fmaf(p0, v0.w, a0[3]);
            a0[4] = fmaf(p0, v1.x, a0[4]); a0[5] = fmaf(p0, v1.y, a0[5]);
            a0[6] = fmaf(p0, v1.z, a0[6]); a0[7] = fmaf(p0, v1.w, a0[7]);
            a1[0] = fmaf(p1, v0.x, a1[0]); a1[1] = fmaf(p1, v0.y, a1[1]);
            a1[2] = fmaf(p1, v0.z, a1[2]); a1[3] = fmaf(p1, v0.w, a1[3]);
            a1[4] = fmaf(p1, v1.x, a1[4]); a1[5] = fmaf(p1, v1.y, a1[5]);
            a1[6] = fmaf(p1, v1.z, a1[6]); a1[7] = fmaf(p1, v1.w, a1[7]);
        }
    }

    float i0 = 1.f / l0, i1 = 1.f / l1;
    float* o0 = &g_att[((size_t)b*TT + q0 + qa)*DM + h*DH + kg*8];
    float* o1 = o0 + DM;
    *(float4*)(o0)     = make_float4(a0[0]*i0, a0[1]*i0, a0[2]*i0, a0[3]*i0);
    *(float4*)(o0 + 4) = make_float4(a0[4]*i0, a0[5]*i0, a0[6]*i0, a0[7]*i0);
    *(float4*)(o1)     = make_float4(a1[0]*i1, a1[1]*i1, a1[2]*i1, a1[3]*i1);
    *(float4*)(o1 + 4) = make_float4(a1[4]*i1, a1[5]*i1, a1[6]*i1, a1[7]*i1);
}

// ---------------------------------------------------------------------------
extern "C" void kernel_launch(void* const* d_in, const int* in_sizes, int n_in,
                              void* d_out, int out_size)
{
    const float* x      = (const float*)d_in[0];  // [4,2048,1024]
    const float* w_qkv  = (const float*)d_in[1];  // [3072,1024]
    const float* w_proj = (const float*)d_in[2];  // [1024,1024]
    float* out = (float*)d_out;                   // [4,2048,1024]

    void *qkv_p = nullptr, *att_p = nullptr;
    cudaGetSymbolAddress(&qkv_p, g_qkv);
    cudaGetSymbolAddress(&att_p, g_att);
    float* qkv = (float*)qkv_p;
    float* att = (float*)att_p;

    cudaFuncSetAttribute(flash_attn, cudaFuncAttributeMaxDynamicSharedMemorySize, 50688);

    // 1) qkv = x @ w_qkv^T   (M=8192, N=3072, K=1024)
    sgemm_nt<<<dim3(3*DM/128, M_TOT/128), 256>>>(x, w_qkv, qkv, 3*DM, DM);

    // 2) flash attention -> g_att (written in [B,T,D] layout)
    flash_attn<<<dim3(TT/64, BB*NH), 256, 50688>>>();

    // 3) out = att @ w_proj^T  (M=8192, N=1024, K=1024)
    sgemm_nt<<<dim3(DM/128, M_TOT/128), 256>>>(att, w_proj, out, DM, DM);
}

// round 3
// speedup vs baseline: 1.0006x; 1.0006x over previous
#include <cuda_runtime.h>
#include <math.h>

#define BB 4
#define TT 2048
#define DM 1024
#define NH 16
#define DH 64
#define M_TOT (BB*TT)   // 8192

// Scratch (allocation-free rule: device globals)
__device__ float g_qkv[(size_t)BB*TT*3*DM];   // [B,T,3D]  ~100.7 MB
__device__ float g_att[(size_t)BB*TT*DM];     // [B,T,D]   ~33.6 MB

// ---------------------------------------------------------------------------
// SGEMM (NT): C[M][N] = sum_k A[M][K][m,k] * B[N][K][n,k]
// BM=BN=128, BK=8, 256 threads, 8x8 per thread. M,N,K all multiples of tile.
// ---------------------------------------------------------------------------
__global__ __launch_bounds__(256) void sgemm_nt(
    const float* __restrict__ A, const float* __restrict__ B,
    float* __restrict__ C, int N, int K)
{
    __shared__ float As[8][128];
    __shared__ float Bs[8][128];
    const int tid = threadIdx.x;
    const float* Ab = A + (size_t)blockIdx.y * 128 * K;
    const float* Bb = B + (size_t)blockIdx.x * 128 * K;
    const int lr = tid >> 1;          // 0..127
    const int lc = (tid & 1) * 4;     // 0 or 4
    const int ty = tid >> 4, tx = tid & 15;

    float acc[8][8];
#pragma unroll
    for (int i = 0; i < 8; i++)
#pragma unroll
        for (int j = 0; j < 8; j++) acc[i][j] = 0.f;

    for (int k0 = 0; k0 < K; k0 += 8) {
        float4 av = *(const float4*)(Ab + (size_t)lr * K + k0 + lc);
        float4 bv = *(const float4*)(Bb + (size_t)lr * K + k0 + lc);
        As[lc+0][lr] = av.x; As[lc+1][lr] = av.y; As[lc+2][lr] = av.z; As[lc+3][lr] = av.w;
        Bs[lc+0][lr] = bv.x; Bs[lc+1][lr] = bv.y; Bs[lc+2][lr] = bv.z; Bs[lc+3][lr] = bv.w;
        __syncthreads();
#pragma unroll
        for (int k = 0; k < 8; k++) {
            float a[8], b[8];
#pragma unroll
            for (int i = 0; i < 8; i++) a[i] = As[k][ty*8 + i];
#pragma unroll
            for (int j = 0; j < 8; j++) b[j] = Bs[k][tx*8 + j];
#pragma unroll
            for (int i = 0; i < 8; i++)
#pragma unroll
                for (int j = 0; j < 8; j++)
                    acc[i][j] = fmaf(a[i], b[j], acc[i][j]);
        }
        __syncthreads();
    }

    float* Cb = C + (size_t)(blockIdx.y*128 + ty*8) * N + blockIdx.x*128 + tx*8;
#pragma unroll
    for (int i = 0; i < 8; i++) {
        *(float4*)(Cb + (size_t)i*N)     = make_float4(acc[i][0], acc[i][1], acc[i][2], acc[i][3]);
        *(float4*)(Cb + (size_t)i*N + 4) = make_float4(acc[i][4], acc[i][5], acc[i][6], acc[i][7]);
    }
}

// ---------------------------------------------------------------------------
// Flash attention, fp32, non-causal. Grid: (T/64, B*H), 256 threads.
// Per block: 64 queries of one (b,h). Loop K/V in 64-row tiles.
// Thread micro-tile: 2 queries (qg = tid>>3) x 8 keys / 8 dims (kg = tid&7).
// Dynamic smem: Qs[64][65] | Ks/Ps union [64][65] | Vs[64][68]  = 50688 B
// ---------------------------------------------------------------------------
extern __shared__ float f_smem[];
#define QS(r,c) f_smem[(r)*65 + (c)]
#define KS(r,c) f_smem[4160 + (r)*65 + (c)]
#define PS(r,c) f_smem[4160 + (r)*65 + (c)]
#define VS(r,c) f_smem[8320 + (r)*68 + (c)]

__global__ __launch_bounds__(256) void flash_attn()
{
    const int tid = threadIdx.x;
    const int qt  = blockIdx.x;          // query tile
    const int bh  = blockIdx.y;
    const int b   = bh >> 4, h = bh & 15;
    const int qg  = tid >> 3;            // 0..31
    const int kg  = tid & 7;             // 0..7
    const int qa  = 2*qg, qb = 2*qg + 1;

    const size_t base = (size_t)b * TT * (3*DM);
    const int qoff = h*DH, koff = DM + h*DH, voff = 2*DM + h*DH;
    const int q0 = qt * 64;

    // Load + pre-scale Q tile
    for (int i = tid; i < 64*64; i += 256) {
        int r = i >> 6, c = i & 63;
        QS(r, c) = g_qkv[base + (size_t)(q0 + r)*(3*DM) + qoff + c] * 0.125f;
    }

    float m0 = -INFINITY, m1 = -INFINITY;
    float l0 = 0.f, l1 = 0.f;
    float a0[8], a1[8];
#pragma unroll
    for (int j = 0; j < 8; j++) { a0[j] = 0.f; a1[j] = 0.f; }

    for (int kt = 0; kt < TT; kt += 64) {
        __syncthreads();  // prior PV done (Ps/Vs free); also orders Q load on iter 0
        for (int i = tid; i < 64*64; i += 256) {
            int r = i >> 6, c = i & 63;
            size_t rb = base + (size_t)(kt + r)*(3*DM);
            KS(r, c) = g_qkv[rb + koff + c];
            VS(r, c) = g_qkv[rb + voff + c];
        }
        __syncthreads();

        // ---- scores: s[q r][kk] for k = kg + 8*kk (conflict-free interleave)
        float s0[8], s1[8];
#pragma unroll
        for (int kk = 0; kk < 8; kk++) { s0[kk] = 0.f; s1[kk] = 0.f; }
#pragma unroll 4
        for (int d = 0; d < 64; d++) {
            float qv0 = QS(qa, d), qv1 = QS(qb, d);
#pragma unroll
            for (int kk = 0; kk < 8; kk++) {
                float kv = KS(kg + 8*kk, d);
                s0[kk] = fmaf(qv0, kv, s0[kk]);
                s1[kk] = fmaf(qv1, kv, s1[kk]);
            }
        }
        __syncthreads();  // Ks reads complete before Ps (aliased) writes

        // ---- online softmax across the 8-lane key group
        float t0 = s0[0], t1 = s1[0];
#pragma unroll
        for (int kk = 1; kk < 8; kk++) { t0 = fmaxf(t0, s0[kk]); t1 = fmaxf(t1, s1[kk]); }
#pragma unroll
        for (int w = 1; w < 8; w <<= 1) {
            t0 = fmaxf(t0, __shfl_xor_sync(0xffffffffu, t0, w));
            t1 = fmaxf(t1, __shfl_xor_sync(0xffffffffu, t1, w));
        }
        float m0n = fmaxf(m0, t0), m1n = fmaxf(m1, t1);
        float c0 = __expf(m0 - m0n), c1 = __expf(m1 - m1n);
        float ls0 = 0.f, ls1 = 0.f;
#pragma unroll
        for (int kk = 0; kk < 8; kk++) {
            float p0 = __expf(s0[kk] - m0n);
            float p1 = __expf(s1[kk] - m1n);
            ls0 += p0; ls1 += p1;
            PS(qa, kg + 8*kk) = p0;
            PS(qb, kg + 8*kk) = p1;
        }
#pragma unroll
        for (int w = 1; w < 8; w <<= 1) {
            ls0 += __shfl_xor_sync(0xffffffffu, ls0, w);
            ls1 += __shfl_xor_sync(0xffffffffu, ls1, w);
        }
        l0 = l0*c0 + ls0;  l1 = l1*c1 + ls1;
        m0 = m0n;          m1 = m1n;
#pragma unroll
        for (int j = 0; j < 8; j++) { a0[j] *= c0; a1[j] *= c1; }
        __syncwarp();  // Ps rows are produced/consumed within one warp

        // ---- PV: thread owns dims d = kg*8 .. kg*8+7 (float4 x2, conflict-free)
#pragma unroll 4
        for (int k = 0; k < 64; k++) {
            float p0 = PS(qa, k), p1 = PS(qb, k);
            float4 v0 = *(const float4*)&VS(k, kg*8);
            float4 v1 = *(const float4*)&VS(k, kg*8 + 4);
            a0[0] = fmaf(p0, v0.x, a0[0]); a0[1] = fmaf(p0, v0.y, a0[1]);
            a0[2] = fmaf(p0, v0.z, a0[2]); a0[3] = fmaf(p0, v0.w, a0[3]);
            a0[4] = fmaf(p0, v1.x, a0[4]); a0[5] = fmaf(p0, v1.y, a0[5]);
            a0[6] = fmaf(p0, v1.z, a0[6]); a0[7] = fmaf(p0, v1.w, a0[7]);
            a1[0] = fmaf(p1, v0.x, a1[0]); a1[1] = fmaf(p1, v0.y, a1[1]);
            a1[2] = fmaf(p1, v0.z, a1[2]); a1[3] = fmaf(p1, v0.w, a1[3]);
            a1[4] = fmaf(p1, v1.x, a1[4]); a1[5] = fmaf(p1, v1.y, a1[5]);
            a1[6] = fmaf(p1, v1.z, a1[6]); a1[7] = fmaf(p1, v1.w, a1[7]);
        }
    }

    float i0 = 1.f / l0, i1 = 1.f / l1;
    float* o0 = &g_att[((size_t)b*TT + q0 + qa)*DM + h*DH + kg*8];
    float* o1 = o0 + DM;
    *(float4*)(o0)     = make_float4(a0[0]*i0, a0[1]*i0, a0[2]*i0, a0[3]*i0);
    *(float4*)(o0 + 4) = make_float4(a0[4]*i0, a0[5]*i0, a0[6]*i0, a0[7]*i0);
    *(float4*)(o1)     = make_float4(a1[0]*i1, a1[1]*i1, a1[2]*i1, a1[3]*i1);
    *(float4*)(o1 + 4) = make_float4(a1[4]*i1, a1[5]*i1, a1[6]*i1, a1[7]*i1);
}

// ---------------------------------------------------------------------------
extern "C" void kernel_launch(void* const* d_in, const int* in_sizes, int n_in,
                              void* d_out, int out_size)
{
    const float* x      = (const float*)d_in[0];  // [4,2048,1024]
    const float* w_qkv  = (const float*)d_in[1];  // [3072,1024]
    const float* w_proj = (const float*)d_in[2];  // [1024,1024]
    float* out = (float*)d_out;                   // [4,2048,1024]

    void *qkv_p = nullptr, *att_p = nullptr;
    cudaGetSymbolAddress(&qkv_p, g_qkv);
    cudaGetSymbolAddress(&att_p, g_att);
    float* qkv = (float*)qkv_p;
    float* att = (float*)att_p;

    cudaFuncSetAttribute(flash_attn, cudaFuncAttributeMaxDynamicSharedMemorySize, 50688);

    // 1) qkv = x @ w_qkv^T   (M=8192, N=3072, K=1024)
    sgemm_nt<<<dim3(3*DM/128, M_TOT/128), 256>>>(x, w_qkv, qkv, 3*DM, DM);

    // 2) flash attention -> g_att (written in [B,T,D] layout)
    flash_attn<<<dim3(TT/64, BB*NH), 256, 50688>>>();

    // 3) out = att @ w_proj^T  (M=8192, N=1024, K=1024)
    sgemm_nt<<<dim3(DM/128, M_TOT/128), 256>>>(att, w_proj, out, DM, DM);
}

// round 5
// speedup vs baseline: 1.2782x; 1.2774x over previous
#include <cuda_runtime.h>
#include <cuda_bf16.h>
#include <math.h>
#include <stdint.h>

#define BB 4
#define TT 2048
#define DM 1024
#define NH 16
#define DH 64
#define M_TOT (BB*TT)   // 8192

// Scratch (allocation-free rule: device globals)
__device__ float g_qkv[(size_t)BB*TT*3*DM];   // [B,T,3D]  ~100.7 MB
__device__ float g_att[(size_t)BB*TT*DM];     // [B,T,D]   ~33.6 MB
// bf16 split planes (reused: x then att; w_qkv then w_proj)
__device__ __nv_bfloat16 g_ah[(size_t)M_TOT*DM];
__device__ __nv_bfloat16 g_al[(size_t)M_TOT*DM];
__device__ __nv_bfloat16 g_wh[(size_t)3*DM*DM];
__device__ __nv_bfloat16 g_wl[(size_t)3*DM*DM];

// ===========================================================================
// Portable (sm_100 base target) tensor-core primitives: mma.sync / ldmatrix /
// cp.async.  NOTE: tcgen05/TMEM are sm_100a-only and this harness compiles at
// sm_100 — do not use them.
// ===========================================================================
__device__ __forceinline__ uint32_t smem_u32(const void* p) {
    uint32_t a;
    asm("{ .reg .u64 t; cvta.to.shared.u64 t, %1; cvt.u32.u64 %0, t; }" : "=r"(a) : "l"(p));
    return a;
}
__device__ __forceinline__ void ldsm4(uint32_t* r, uint32_t addr) {
    asm volatile("ldmatrix.sync.aligned.m8n8.x4.shared.b16 {%0,%1,%2,%3}, [%4];"
        : "=r"(r[0]), "=r"(r[1]), "=r"(r[2]), "=r"(r[3]) : "r"(addr));
}
__device__ __forceinline__ void ldsm2(uint32_t* r, uint32_t addr) {
    asm volatile("ldmatrix.sync.aligned.m8n8.x2.shared.b16 {%0,%1}, [%2];"
        : "=r"(r[0]), "=r"(r[1]) : "r"(addr));
}
__device__ __forceinline__ void mma_bf16(float* d, const uint32_t* a, const uint32_t* b) {
    asm volatile("mma.sync.aligned.m16n8k16.row.col.f32.bf16.bf16.f32 "
        "{%0,%1,%2,%3}, {%4,%5,%6,%7}, {%8,%9}, {%0,%1,%2,%3};"
        : "+f"(d[0]), "+f"(d[1]), "+f"(d[2]), "+f"(d[3])
        : "r"(a[0]), "r"(a[1]), "r"(a[2]), "r"(a[3]), "r"(b[0]), "r"(b[1]));
}
#define CP_ASYNC16(s, g) \
    asm volatile("cp.async.cg.shared.global [%0], [%1], 16;" :: "r"(s), "l"(g))
#define CP_COMMIT() asm volatile("cp.async.commit_group;" ::: "memory")
template <int N> __device__ __forceinline__ void cp_wait() {
    asm volatile("cp.async.wait_group %0;" :: "n"(N) : "memory");
}

// ===========================================================================
// fp32 -> bf16 (hi, lo) split:  v = hi + lo + O(2^-17 |v|)
// ===========================================================================
__global__ __launch_bounds__(256) void split_bf16(
    const float* __restrict__ src, __nv_bfloat16* __restrict__ hi,
    __nv_bfloat16* __restrict__ lo, int n)
{
    int i = (blockIdx.x * 256 + threadIdx.x) * 4;
    if (i >= n) return;
    float4 v = *(const float4*)(src + i);
    __nv_bfloat16 h0 = __float2bfloat16(v.x), h1 = __float2bfloat16(v.y);
    __nv_bfloat16 h2 = __float2bfloat16(v.z), h3 = __float2bfloat16(v.w);
    __nv_bfloat16 l0 = __float2bfloat16(v.x - __bfloat162float(h0));
    __nv_bfloat16 l1 = __float2bfloat16(v.y - __bfloat162float(h1));
    __nv_bfloat16 l2 = __float2bfloat16(v.z - __bfloat162float(h2));
    __nv_bfloat16 l3 = __float2bfloat16(v.w - __bfloat162float(h3));
    uint2 hp, lp;
    hp.x = (uint32_t)__bfloat16_as_ushort(h0) | ((uint32_t)__bfloat16_as_ushort(h1) << 16);
    hp.y = (uint32_t)__bfloat16_as_ushort(h2) | ((uint32_t)__bfloat16_as_ushort(h3) << 16);
    lp.x = (uint32_t)__bfloat16_as_ushort(l0) | ((uint32_t)__bfloat16_as_ushort(l1) << 16);
    lp.y = (uint32_t)__bfloat16_as_ushort(l2) | ((uint32_t)__bfloat16_as_ushort(l3) << 16);
    *(uint2*)(hi + i) = hp;
    *(uint2*)(lo + i) = lp;
}

// ===========================================================================
// HMMA bf16-split GEMM (NT): C[M][N] = A[M][K] * B[N][K]^T, fp32 accumulate.
// CTA 128x128, 8 warps (2x4), warp tile 64x32, BK=32, double-buffered cp.async.
// smem rows padded to 40 halves (80 B) -> ldmatrix conflict-free.
// ===========================================================================
#define BK 32
#define ABYTES (128*80)              // one operand plane per stage: 10240 B
#define STG    (4*ABYTES)            // AH AL BH BL
#define GSMEM  (2*STG)               // 81920 B

__global__ __launch_bounds__(256, 1) void gemm_mma(
    const __nv_bfloat16* __restrict__ Ah, const __nv_bfloat16* __restrict__ Al,
    const __nv_bfloat16* __restrict__ Bh, const __nv_bfloat16* __restrict__ Bl,
    float* __restrict__ C, int N, int K)
{
    extern __shared__ char smem[];
    const uint32_t sb = smem_u32(smem);
    const int tid = threadIdx.x, lane = tid & 31, wid = tid >> 5;
    const int wm = wid >> 2, wn = wid & 3;         // 2 x 4 warp grid
    const int mBlk = blockIdx.y * 128, nBlk = blockIdx.x * 128;

    float acc[4][4][4];
#pragma unroll
    for (int mt = 0; mt < 4; mt++)
#pragma unroll
        for (int nt = 0; nt < 4; nt++)
#pragma unroll
            for (int j = 0; j < 4; j++) acc[mt][nt][j] = 0.f;

    // per-thread copy slots: i in [0,512): row=i>>2, 16B chunk=i&3
    const int r0c = tid >> 1;                  // not used; keep index math below
    (void)r0c;

    const int NCH = K / BK;

    auto load_stage = [&](int s, int k0) {
        uint32_t so = sb + (s ? STG : 0);
#pragma unroll
        for (int i = tid; i < 512; i += 256) {
            int r = i >> 2, ch = i & 3;
            uint32_t d = so + (uint32_t)r * 80 + ch * 16;
            size_t goA = (size_t)(mBlk + r) * K + k0 + ch * 8;
            size_t goB = (size_t)(nBlk + r) * K + k0 + ch * 8;
            CP_ASYNC16(d,              Ah + goA);
            CP_ASYNC16(d + ABYTES,     Al + goA);
            CP_ASYNC16(d + 2*ABYTES,   Bh + goB);
            CP_ASYNC16(d + 3*ABYTES,   Bl + goB);
        }
        CP_COMMIT();
    };

    load_stage(0, 0);

    for (int c = 0; c < NCH; c++) {
        if (c + 1 < NCH) { load_stage((c + 1) & 1, (c + 1) * BK); cp_wait<1>(); }
        else             { cp_wait<0>(); }
        __syncthreads();

        uint32_t so = sb + ((c & 1) ? STG : 0);
        const uint32_t aRow = wm * 64 + (lane & 15);
        const uint32_t bRow = wn * 32 + (lane & 7);
#pragma unroll
        for (int ks = 0; ks < 2; ks++) {
            const uint32_t ak = ks * 16 + (lane >> 4) * 8;         // halves
            const uint32_t bk = ks * 16 + ((lane >> 3) & 1) * 8;
            uint32_t ah[4][4], al[4][4];
#pragma unroll
            for (int mt = 0; mt < 4; mt++) {
                uint32_t addr = so + (aRow + mt * 16) * 80 + ak * 2;
                ldsm4(ah[mt], addr);
                ldsm4(al[mt], addr + ABYTES);
            }
#pragma unroll
            for (int nt = 0; nt < 4; nt++) {
                uint32_t baddr = so + 2*ABYTES + (bRow + nt * 8) * 80 + bk * 2;
                uint32_t bh[2], bl[2];
                ldsm2(bh, baddr);
                ldsm2(bl, baddr + ABYTES);
#pragma unroll
                for (int mt = 0; mt < 4; mt++) {
                    mma_bf16(acc[mt][nt], ah[mt], bh);
                    mma_bf16(acc[mt][nt], ah[mt], bl);
                    mma_bf16(acc[mt][nt], al[mt], bh);
                }
            }
        }
        __syncthreads();
    }

    // epilogue: direct float2 stores
    const int row0 = mBlk + wm * 64, col0 = nBlk + wn * 32;
#pragma unroll
    for (int mt = 0; mt < 4; mt++) {
        int r = row0 + mt * 16 + (lane >> 2);
#pragma unroll
        for (int nt = 0; nt < 4; nt++) {
            int cc = col0 + nt * 8 + (lane & 3) * 2;
            *(float2*)(C + (size_t)r * N + cc)       = make_float2(acc[mt][nt][0], acc[mt][nt][1]);
            *(float2*)(C + (size_t)(r + 8) * N + cc) = make_float2(acc[mt][nt][2], acc[mt][nt][3]);
        }
    }
}

// ---------------------------------------------------------------------------
// Flash attention, fp32, non-causal (unchanged — passing config from R2/R3).
// ---------------------------------------------------------------------------
#define QS(r,c) f_smem[(r)*65 + (c)]
#define KS(r,c) f_smem[4160 + (r)*65 + (c)]
#define PS(r,c) f_smem[4160 + (r)*65 + (c)]
#define VS(r,c) f_smem[8320 + (r)*68 + (c)]

__global__ __launch_bounds__(256) void flash_attn()
{
    extern __shared__ float f_smem[];
    const int tid = threadIdx.x;
    const int qt  = blockIdx.x;
    const int bh  = blockIdx.y;
    const int b   = bh >> 4, h = bh & 15;
    const int qg  = tid >> 3;
    const int kg  = tid & 7;
    const int qa  = 2*qg, qb = 2*qg + 1;

    const size_t base = (size_t)b * TT * (3*DM);
    const int qoff = h*DH, koff = DM + h*DH, voff = 2*DM + h*DH;
    const int q0 = qt * 64;

    for (int i = tid; i < 64*64; i += 256) {
        int r = i >> 6, c = i & 63;
        QS(r, c) = g_qkv[base + (size_t)(q0 + r)*(3*DM) + qoff + c] * 0.125f;
    }

    float m0 = -INFINITY, m1 = -INFINITY;
    float l0 = 0.f, l1 = 0.f;
    float a0[8], a1[8];
#pragma unroll
    for (int j = 0; j < 8; j++) { a0[j] = 0.f; a1[j] = 0.f; }

    for (int kt = 0; kt < TT; kt += 64) {
        __syncthreads();
        for (int i = tid; i < 64*64; i += 256) {
            int r = i >> 6, c = i & 63;
            size_t rb = base + (size_t)(kt + r)*(3*DM);
            KS(r, c) = g_qkv[rb + koff + c];
            VS(r, c) = g_qkv[rb + voff + c];
        }
        __syncthreads();

        float s0[8], s1[8];
#pragma unroll
        for (int kk = 0; kk < 8; kk++) { s0[kk] = 0.f; s1[kk] = 0.f; }
#pragma unroll 4
        for (int d = 0; d < 64; d++) {
            float qv0 = QS(qa, d), qv1 = QS(qb, d);
#pragma unroll
            for (int kk = 0; kk < 8; kk++) {
                float kv = KS(kg + 8*kk, d);
                s0[kk] = fmaf(qv0, kv, s0[kk]);
                s1[kk] = fmaf(qv1, kv, s1[kk]);
            }
        }
        __syncthreads();

        float t0 = s0[0], t1 = s1[0];
#pragma unroll
        for (int kk = 1; kk < 8; kk++) { t0 = fmaxf(t0, s0[kk]); t1 = fmaxf(t1, s1[kk]); }
#pragma unroll
        for (int w = 1; w < 8; w <<= 1) {
            t0 = fmaxf(t0, __shfl_xor_sync(0xffffffffu, t0, w));
            t1 = fmaxf(t1, __shfl_xor_sync(0xffffffffu, t1, w));
        }
        float m0n = fmaxf(m0, t0), m1n = fmaxf(m1, t1);
        float c0 = __expf(m0 - m0n), c1 = __expf(m1 - m1n);
        float ls0 = 0.f, ls1 = 0.f;
#pragma unroll
        for (int kk = 0; kk < 8; kk++) {
            float p0 = __expf(s0[kk] - m0n);
            float p1 = __expf(s1[kk] - m1n);
            ls0 += p0; ls1 += p1;
            PS(qa, kg + 8*kk) = p0;
            PS(qb, kg + 8*kk) = p1;
        }
#pragma unroll
        for (int w = 1; w < 8; w <<= 1) {
            ls0 += __shfl_xor_sync(0xffffffffu, ls0, w);
            ls1 += __shfl_xor_sync(0xffffffffu, ls1, w);
        }
        l0 = l0*c0 + ls0;  l1 = l1*c1 + ls1;
        m0 = m0n;          m1 = m1n;
#pragma unroll
        for (int j = 0; j < 8; j++) { a0[j] *= c0; a1[j] *= c1; }
        __syncwarp();

#pragma unroll 4
        for (int k = 0; k < 64; k++) {
            float p0 = PS(qa, k), p1 = PS(qb, k);
            float4 v0 = *(const float4*)&VS(k, kg*8);
            float4 v1 = *(const float4*)&VS(k, kg*8 + 4);
            a0[0] = fmaf(p0, v0.x, a0[0]); a0[1] = fmaf(p0, v0.y, a0[1]);
            a0[2] = fmaf(p0, v0.z, a0[2]); a0[3] = fmaf(p0, v0.w, a0[3]);
            a0[4] = fmaf(p0, v1.x, a0[4]); a0[5] = fmaf(p0, v1.y, a0[5]);
            a0[6] = fmaf(p0, v1.z, a0[6]); a0[7] = fmaf(p0, v1.w, a0[7]);
            a1[0] = fmaf(p1, v0.x, a1[0]); a1[1] = fmaf(p1, v0.y, a1[1]);
            a1[2] = fmaf(p1, v0.z, a1[2]); a1[3] = fmaf(p1, v0.w, a1[3]);
            a1[4] = fmaf(p1, v1.x, a1[4]); a1[5] = fmaf(p1, v1.y, a1[5]);
            a1[6] = fmaf(p1, v1.z, a1[6]); a1[7] = fmaf(p1, v1.w, a1[7]);
        }
    }

    float i0 = 1.f / l0, i1 = 1.f / l1;
    float* o0 = &g_att[((size_t)b*TT + q0 + qa)*DM + h*DH + kg*8];
    float* o1 = o0 + DM;
    *(float4*)(o0)     = make_float4(a0[0]*i0, a0[1]*i0, a0[2]*i0, a0[3]*i0);
    *(float4*)(o0 + 4) = make_float4(a0[4]*i0, a0[5]*i0, a0[6]*i0, a0[7]*i0);
    *(float4*)(o1)     = make_float4(a1[0]*i1, a1[1]*i1, a1[2]*i1, a1[3]*i1);
    *(float4*)(o1 + 4) = make_float4(a1[4]*i1, a1[5]*i1, a1[6]*i1, a1[7]*i1);
}

// ---------------------------------------------------------------------------
extern "C" void kernel_launch(void* const* d_in, const int* in_sizes, int n_in,
                              void* d_out, int out_size)
{
    const float* x      = (const float*)d_in[0];  // [4,2048,1024]
    const float* w_qkv  = (const float*)d_in[1];  // [3072,1024]
    const float* w_proj = (const float*)d_in[2];  // [1024,1024]
    float* out = (float*)d_out;                   // [4,2048,1024]

    void *qkv_p, *att_p, *ah_p, *al_p, *wh_p, *wl_p;
    cudaGetSymbolAddress(&qkv_p, g_qkv);
    cudaGetSymbolAddress(&att_p, g_att);
    cudaGetSymbolAddress(&ah_p, g_ah);
    cudaGetSymbolAddress(&al_p, g_al);
    cudaGetSymbolAddress(&wh_p, g_wh);
    cudaGetSymbolAddress(&wl_p, g_wl);
    float* qkv = (float*)qkv_p;
    float* att = (float*)att_p;
    __nv_bfloat16 *ah = (__nv_bfloat16*)ah_p, *al = (__nv_bfloat16*)al_p;
    __nv_bfloat16 *wh = (__nv_bfloat16*)wh_p, *wl = (__nv_bfloat16*)wl_p;

    cudaFuncSetAttribute(gemm_mma, cudaFuncAttributeMaxDynamicSharedMemorySize, GSMEM);
    cudaFuncSetAttribute(flash_attn, cudaFuncAttributeMaxDynamicSharedMemorySize, 50688);

    const int nX = M_TOT * DM, nWq = 3 * DM * DM, nWp = DM * DM;

    // 1) split x and w_qkv; qkv = x @ w_qkv^T  (M=8192, N=3072, K=1024)
    split_bf16<<<nX / 1024, 256>>>(x, ah, al, nX);
    split_bf16<<<nWq / 1024, 256>>>(w_qkv, wh, wl, nWq);
    gemm_mma<<<dim3(3*DM/128, M_TOT/128), 256, GSMEM>>>(ah, al, wh, wl, qkv, 3*DM, DM);

    // 2) flash attention -> g_att ([B,T,D] layout)
    flash_attn<<<dim3(TT/64, BB*NH), 256, 50688>>>();

    // 3) split att and w_proj; out = att @ w_proj^T  (M=8192, N=1024, K=1024)
    split_bf16<<<nX / 1024, 256>>>(att, ah, al, nX);
    split_bf16<<<nWp / 1024, 256>>>(w_proj, wh, wl, nWp);
    gemm_mma<<<dim3(DM/128, M_TOT/128), 256, GSMEM>>>(ah, al, wh, wl, out, DM, DM);
}

// round 7
// speedup vs baseline: 3.8009x; 2.9737x over previous
#include <cuda_runtime.h>
#include <cuda_bf16.h>
#include <math.h>
#include <stdint.h>

#define BB 4
#define TT 2048
#define DM 1024
#define NH 16
#define DH 64
#define M_TOT (BB*TT)   // 8192

// Scratch (allocation-free rule: device globals), all bf16 split planes
__device__ __nv_bfloat16 g_qkvh[(size_t)BB*TT*3*DM];  // qkv hi [B,T,3D]
__device__ __nv_bfloat16 g_qkvl[(size_t)BB*TT*3*DM];  // qkv lo
__device__ __nv_bfloat16 g_ah[(size_t)M_TOT*DM];      // x-split, then att-split (hi)
__device__ __nv_bfloat16 g_al[(size_t)M_TOT*DM];      // (lo)
__device__ __nv_bfloat16 g_wh[(size_t)3*DM*DM];       // weight splits (hi)
__device__ __nv_bfloat16 g_wl[(size_t)3*DM*DM];       // (lo)

// ===========================================================================
// Portable (sm_100 base target) tensor-core primitives. tcgen05 is sm_100a-
// only and this harness compiles at sm_100 — mma.sync/ldmatrix/cp.async only.
// ===========================================================================
__device__ __forceinline__ uint32_t smem_u32(const void* p) {
    uint32_t a;
    asm("{ .reg .u64 t; cvta.to.shared.u64 t, %1; cvt.u32.u64 %0, t; }" : "=r"(a) : "l"(p));
    return a;
}
__device__ __forceinline__ void ldsm4(uint32_t* r, uint32_t addr) {
    asm volatile("ldmatrix.sync.aligned.m8n8.x4.shared.b16 {%0,%1,%2,%3}, [%4];"
        : "=r"(r[0]), "=r"(r[1]), "=r"(r[2]), "=r"(r[3]) : "r"(addr));
}
__device__ __forceinline__ void ldsm4t(uint32_t* r, uint32_t addr) {
    asm volatile("ldmatrix.sync.aligned.m8n8.x4.trans.shared.b16 {%0,%1,%2,%3}, [%4];"
        : "=r"(r[0]), "=r"(r[1]), "=r"(r[2]), "=r"(r[3]) : "r"(addr));
}
__device__ __forceinline__ void ldsm2(uint32_t* r, uint32_t addr) {
    asm volatile("ldmatrix.sync.aligned.m8n8.x2.shared.b16 {%0,%1}, [%2];"
        : "=r"(r[0]), "=r"(r[1]) : "r"(addr));
}
__device__ __forceinline__ void mma_bf16(float* d, const uint32_t* a, const uint32_t* b) {
    asm volatile("mma.sync.aligned.m16n8k16.row.col.f32.bf16.bf16.f32 "
        "{%0,%1,%2,%3}, {%4,%5,%6,%7}, {%8,%9}, {%0,%1,%2,%3};"
        : "+f"(d[0]), "+f"(d[1]), "+f"(d[2]), "+f"(d[3])
        : "r"(a[0]), "r"(a[1]), "r"(a[2]), "r"(a[3]), "r"(b[0]), "r"(b[1]));
}
#define CP_ASYNC16(s, g) \
    asm volatile("cp.async.cg.shared.global [%0], [%1], 16;" :: "r"(s), "l"(g))
#define CP_COMMIT() asm volatile("cp.async.commit_group;" ::: "memory")
template <int N> __device__ __forceinline__ void cp_wait() {
    asm volatile("cp.async.wait_group %0;" :: "n"(N) : "memory");
}
__device__ __forceinline__ float ex2(float x) {
    float y;
    asm("ex2.approx.ftz.f32 %0, %1;" : "=f"(y) : "f"(x));
    return y;
}
__device__ __forceinline__ void splitpack(float a, float b, uint32_t& hi, uint32_t& lo) {
    __nv_bfloat16 ha = __float2bfloat16(a), hb = __float2bfloat16(b);
    __nv_bfloat16 la = __float2bfloat16(a - __bfloat162float(ha));
    __nv_bfloat16 lb = __float2bfloat16(b - __bfloat162float(hb));
    hi = (uint32_t)__bfloat16_as_ushort(ha) | ((uint32_t)__bfloat16_as_ushort(hb) << 16);
    lo = (uint32_t)__bfloat16_as_ushort(la) | ((uint32_t)__bfloat16_as_ushort(lb) << 16);
}

// ===========================================================================
// fp32 -> bf16 (hi, lo) split pass:  v = hi + lo + O(2^-17 |v|)
// ===========================================================================
__global__ __launch_bounds__(256) void split_bf16(
    const float* __restrict__ src, __nv_bfloat16* __restrict__ hi,
    __nv_bfloat16* __restrict__ lo, int n)
{
    int i = (blockIdx.x * 256 + threadIdx.x) * 4;
    if (i >= n) return;
    float4 v = *(const float4*)(src + i);
    uint2 hp, lp;
    splitpack(v.x, v.y, hp.x, lp.x);
    splitpack(v.z, v.w, hp.y, lp.y);
    *(uint2*)(hi + i) = hp;
    *(uint2*)(lo + i) = lp;
}

// ===========================================================================
// HMMA bf16-split GEMM (NT): C = A * B^T, fp32 accumulate.
// CTA 128x128, 8 warps (2x4), warp tile 64x32, BK=32, double-buffered cp.async.
// Rows: 32 halves = 64 B data padded to 80 B (ldmatrix conflict-free).
// SPLIT=true: write bf16 hi/lo planes (Ch/Cl).  SPLIT=false: write fp32 C.
// ===========================================================================
#define BK 32
#define ABYTES (128*80)
#define STG    (4*ABYTES)
#define GSMEM  (2*STG)               // 81920 B

template <bool SPLIT>
__global__ __launch_bounds__(256, 1) void gemm_mma(
    const __nv_bfloat16* __restrict__ Ah, const __nv_bfloat16* __restrict__ Al,
    const __nv_bfloat16* __restrict__ Bh, const __nv_bfloat16* __restrict__ Bl,
    float* __restrict__ C, __nv_bfloat16* __restrict__ Ch, __nv_bfloat16* __restrict__ Cl,
    int N, int K)
{
    extern __shared__ char smem[];
    const uint32_t sb = smem_u32(smem);
    const int tid = threadIdx.x, lane = tid & 31, wid = tid >> 5;
    const int wm = wid >> 2, wn = wid & 3;
    const int mBlk = blockIdx.y * 128, nBlk = blockIdx.x * 128;

    float acc[4][4][4];
#pragma unroll
    for (int mt = 0; mt < 4; mt++)
#pragma unroll
        for (int nt = 0; nt < 4; nt++)
#pragma unroll
            for (int j = 0; j < 4; j++) acc[mt][nt][j] = 0.f;

    const int NCH = K / BK;

    auto load_stage = [&](int s, int k0) {
        uint32_t so = sb + (s ? STG : 0);
#pragma unroll
        for (int i = tid; i < 512; i += 256) {
            int r = i >> 2, ch = i & 3;
            uint32_t d = so + (uint32_t)r * 80 + ch * 16;
            size_t goA = (size_t)(mBlk + r) * K + k0 + ch * 8;
            size_t goB = (size_t)(nBlk + r) * K + k0 + ch * 8;
            CP_ASYNC16(d,            Ah + goA);
            CP_ASYNC16(d + ABYTES,   Al + goA);
            CP_ASYNC16(d + 2*ABYTES, Bh + goB);
            CP_ASYNC16(d + 3*ABYTES, Bl + goB);
        }
        CP_COMMIT();
    };

    load_stage(0, 0);

    for (int c = 0; c < NCH; c++) {
        if (c + 1 < NCH) { load_stage((c + 1) & 1, (c + 1) * BK); cp_wait<1>(); }
        else             { cp_wait<0>(); }
        __syncthreads();

        uint32_t so = sb + ((c & 1) ? STG : 0);
        const uint32_t aRow = wm * 64 + (lane & 15);
        const uint32_t bRow = wn * 32 + (lane & 7);
#pragma unroll
        for (int ks = 0; ks < 2; ks++) {
            const uint32_t ak = ks * 16 + (lane >> 4) * 8;
            const uint32_t bk = ks * 16 + ((lane >> 3) & 1) * 8;
            uint32_t ah[4][4], al[4][4];
#pragma unroll
            for (int mt = 0; mt < 4; mt++) {
                uint32_t addr = so + (aRow + mt * 16) * 80 + ak * 2;
                ldsm4(ah[mt], addr);
                ldsm4(al[mt], addr + ABYTES);
            }
#pragma unroll
            for (int nt = 0; nt < 4; nt++) {
                uint32_t baddr = so + 2*ABYTES + (bRow + nt * 8) * 80 + bk * 2;
                uint32_t bh[2], bl[2];
                ldsm2(bh, baddr);
                ldsm2(bl, baddr + ABYTES);
#pragma unroll
                for (int mt = 0; mt < 4; mt++) {
                    mma_bf16(acc[mt][nt], ah[mt], bh);
                    mma_bf16(acc[mt][nt], ah[mt], bl);
                    mma_bf16(acc[mt][nt], al[mt], bh);
                }
            }
        }
        __syncthreads();
    }

    const int row0 = mBlk + wm * 64, col0 = nBlk + wn * 32;
#pragma unroll
    for (int mt = 0; mt < 4; mt++) {
        int r = row0 + mt * 16 + (lane >> 2);
#pragma unroll
        for (int nt = 0; nt < 4; nt++) {
            int cc = col0 + nt * 8 + (lane & 3) * 2;
            if (SPLIT) {
                uint32_t h0, l0, h1, l1;
                splitpack(acc[mt][nt][0], acc[mt][nt][1], h0, l0);
                splitpack(acc[mt][nt][2], acc[mt][nt][3], h1, l1);
                *(uint32_t*)(Ch + (size_t)r * N + cc)       = h0;
                *(uint32_t*)(Cl + (size_t)r * N + cc)       = l0;
                *(uint32_t*)(Ch + (size_t)(r + 8) * N + cc) = h1;
                *(uint32_t*)(Cl + (size_t)(r + 8) * N + cc) = l1;
            } else {
                *(float2*)(C + (size_t)r * N + cc)       = make_float2(acc[mt][nt][0], acc[mt][nt][1]);
                *(float2*)(C + (size_t)(r + 8) * N + cc) = make_float2(acc[mt][nt][2], acc[mt][nt][3]);
            }
        }
    }
}

// ===========================================================================
// Tensor-core flash attention (FA2-style), bf16-split everywhere, fp32 accum.
// Grid (T/128, B*H), 256 threads (8 warps, 16 q-rows each). Key tiles of 64.
// Rows: 64 halves = 128 B data padded to 144 B (ldmatrix conflict-free:
// 8 rows * 144 B -> word offsets {0,4,8,...,28} mod 32 banks).
// smem: Qh Ql (128x144B) | 2 stages x {Kh,Kl,Vh,Vl} (64x144B each) = 110592 B.
// ===========================================================================
#define FROW 144
#define QPL  (128*FROW)      // 18432 per Q plane
#define KVPL (64*FROW)       // 9216 per K/V plane
#define SQH 0
#define SQL QPL
#define SKV (2*QPL)          // 36864
#define KVSTG (4*KVPL)       // 36864 per stage
#define FSMEM (SKV + 2*KVSTG) // 110592

__global__ __launch_bounds__(256, 1) void flash_tc(
    const __nv_bfloat16* __restrict__ Ph, const __nv_bfloat16* __restrict__ Pl,
    __nv_bfloat16* __restrict__ Oh, __nv_bfloat16* __restrict__ Ol)
{
    extern __shared__ char smem[];
    const uint32_t sb = smem_u32(smem);
    const int tid = threadIdx.x, lane = tid & 31, wid = tid >> 5;
    const int qt = blockIdx.x, bh = blockIdx.y;
    const int b = bh >> 4, h = bh & 15;
    const size_t rowbase = (size_t)b * TT;
    const int q0 = qt * 128;
    const int hoff = h * DH;

    // ---- Q tile (hi/lo), 128 rows x 64 halves, cp.async
#pragma unroll
    for (int i = tid; i < 2048; i += 256) {
        int pl = i >> 10, r = (i >> 3) & 127, ch = i & 7;
        const __nv_bfloat16* src = (pl ? Pl : Ph) + (rowbase + q0 + r) * 3*DM + hoff + ch * 8;
        CP_ASYNC16(sb + (pl ? SQL : SQH) + r * FROW + ch * 16, src);
    }
    auto load_kv = [&](int s, int kt) {
        uint32_t so = sb + SKV + s * KVSTG;
#pragma unroll
        for (int i = tid; i < 2048; i += 256) {
            int p = i >> 9, r = (i >> 3) & 63, ch = i & 7;
            const __nv_bfloat16* basep = (p & 1) ? Pl : Ph;
            int sec = (p >> 1) ? 2*DM : DM;
            const __nv_bfloat16* src = basep + (rowbase + kt*64 + r) * 3*DM + sec + hoff + ch * 8;
            CP_ASYNC16(so + p * KVPL + r * FROW + ch * 16, src);
        }
    };
    load_kv(0, 0);
    CP_COMMIT();

    const int wq = wid * 16;
    const float CSC = 0.125f * 1.4426950408889634f;   // scale * log2(e)
    float o[8][4];
#pragma unroll
    for (int j = 0; j < 8; j++)
#pragma unroll
        for (int i = 0; i < 4; i++) o[j][i] = 0.f;
    float m0 = -1e30f, m1 = -1e30f, l0 = 0.f, l1 = 0.f;

    for (int kt = 0; kt < TT/64; kt++) {
        if (kt + 1 < TT/64) { load_kv((kt + 1) & 1, kt + 1); CP_COMMIT(); cp_wait<1>(); }
        else                { cp_wait<0>(); }
        __syncthreads();
        const uint32_t kvb = sb + SKV + (kt & 1) * KVSTG;

        // ---- S = Q K^T  (split: QhKh + QhKl + QlKh)
        float s[8][4];
#pragma unroll
        for (int j = 0; j < 8; j++)
#pragma unroll
            for (int i = 0; i < 4; i++) s[j][i] = 0.f;
#pragma unroll
        for (int ks = 0; ks < 4; ks++) {
            uint32_t qaddr = sb + SQH + (wq + (lane & 15)) * FROW + (ks*16 + (lane >> 4)*8) * 2;
            uint32_t qh[4], ql[4];
            ldsm4(qh, qaddr);
            ldsm4(ql, qaddr + SQL);
#pragma unroll
            for (int np = 0; np < 4; np++) {
                uint32_t kaddr = kvb + (np*16 + (lane & 15)) * FROW + (ks*16 + (lane >> 4)*8) * 2;
                uint32_t kh[4], kl[4];
                ldsm4(kh, kaddr);
                ldsm4(kl, kaddr + KVPL);
                uint32_t b0h[2] = {kh[0], kh[2]}, b1h[2] = {kh[1], kh[3]};
                uint32_t b0l[2] = {kl[0], kl[2]}, b1l[2] = {kl[1], kl[3]};
                mma_bf16(s[2*np],   qh, b0h);
                mma_bf16(s[2*np],   qh, b0l);
                mma_bf16(s[2*np],   ql, b0h);
                mma_bf16(s[2*np+1], qh, b1h);
                mma_bf16(s[2*np+1], qh, b1l);
                mma_bf16(s[2*np+1], ql, b1h);
            }
        }

        // ---- online softmax (log2 domain, scale folded in)
#pragma unroll
        for (int j = 0; j < 8; j++)
#pragma unroll
            for (int i = 0; i < 4; i++) s[j][i] *= CSC;
        float t0 = -1e30f, t1 = -1e30f;
#pragma unroll
        for (int j = 0; j < 8; j++) {
            t0 = fmaxf(t0, fmaxf(s[j][0], s[j][1]));
            t1 = fmaxf(t1, fmaxf(s[j][2], s[j][3]));
        }
        t0 = fmaxf(t0, __shfl_xor_sync(0xffffffffu, t0, 1));
        t0 = fmaxf(t0, __shfl_xor_sync(0xffffffffu, t0, 2));
        t1 = fmaxf(t1, __shfl_xor_sync(0xffffffffu, t1, 1));
        t1 = fmaxf(t1, __shfl_xor_sync(0xffffffffu, t1, 2));
        float m0n = fmaxf(m0, t0), m1n = fmaxf(m1, t1);
        float r0 = ex2(m0 - m0n), r1 = ex2(m1 - m1n);
        m0 = m0n; m1 = m1n;

        float ls0 = 0.f, ls1 = 0.f;
        uint32_t aph[4][4], apl[4][4];
#pragma unroll
        for (int j = 0; j < 8; j++) {
            float p0 = ex2(s[j][0] - m0), p1 = ex2(s[j][1] - m0);
            float p2 = ex2(s[j][2] - m1), p3 = ex2(s[j][3] - m1);
            ls0 += p0 + p1; ls1 += p2 + p3;
            int jj = j >> 1, rb = (j & 1) * 2;
            splitpack(p0, p1, aph[jj][rb],     apl[jj][rb]);
            splitpack(p2, p3, aph[jj][rb + 1], apl[jj][rb + 1]);
        }
        ls0 += __shfl_xor_sync(0xffffffffu, ls0, 1);
        ls0 += __shfl_xor_sync(0xffffffffu, ls0, 2);
        ls1 += __shfl_xor_sync(0xffffffffu, ls1, 1);
        ls1 += __shfl_xor_sync(0xffffffffu, ls1, 2);
        l0 = l0 * r0 + ls0;
        l1 = l1 * r1 + ls1;
#pragma unroll
        for (int j = 0; j < 8; j++) {
            o[j][0] *= r0; o[j][1] *= r0; o[j][2] *= r1; o[j][3] *= r1;
        }

        // ---- O += P V  (split: PhVh + PhVl + PlVh), V via ldmatrix.trans
#pragma unroll
        for (int jj = 0; jj < 4; jj++) {
#pragma unroll
            for (int np = 0; np < 4; np++) {
                uint32_t vaddr = kvb + 2*KVPL + (jj*16 + (lane & 15)) * FROW + (np*16 + (lane >> 4)*8) * 2;
                uint32_t vh[4], vl[4];
                ldsm4t(vh, vaddr);
                ldsm4t(vl, vaddr + KVPL);
                uint32_t bh0[2] = {vh[0], vh[1]}, bh1[2] = {vh[2], vh[3]};
                uint32_t bl0[2] = {vl[0], vl[1]}, bl1[2] = {vl[2], vl[3]};
                mma_bf16(o[2*np],   aph[jj], bh0);
                mma_bf16(o[2*np],   aph[jj], bl0);
                mma_bf16(o[2*np],   apl[jj], bh0);
                mma_bf16(o[2*np+1], aph[jj], bh1);
                mma_bf16(o[2*np+1], aph[jj], bl1);
                mma_bf16(o[2*np+1], apl[jj], bh1);
            }
        }
        __syncthreads();
    }

    // ---- epilogue: normalize, split, write att hi/lo planes [B,T,D]
    float inv0 = 1.f / l0, inv1 = 1.f / l1;
    const size_t rA = rowbase + q0 + wq + (lane >> 2);
    const size_t rB = rA + 8;
#pragma unroll
    for (int j = 0; j < 8; j++) {
        int col = hoff + j * 8 + (lane & 3) * 2;
        uint32_t h0, lo0, h1, lo1;
        splitpack(o[j][0] * inv0, o[j][1] * inv0, h0, lo0);
        splitpack(o[j][2] * inv1, o[j][3] * inv1, h1, lo1);
        *(uint32_t*)(Oh + rA * DM + col) = h0;
        *(uint32_t*)(Ol + rA * DM + col) = lo0;
        *(uint32_t*)(Oh + rB * DM + col) = h1;
        *(uint32_t*)(Ol + rB * DM + col) = lo1;
    }
}

// ---------------------------------------------------------------------------
extern "C" void kernel_launch(void* const* d_in, const int* in_sizes, int n_in,
                              void* d_out, int out_size)
{
    const float* x      = (const float*)d_in[0];  // [4,2048,1024]
    const float* w_qkv  = (const float*)d_in[1];  // [3072,1024]
    const float* w_proj = (const float*)d_in[2];  // [1024,1024]
    float* out = (float*)d_out;                   // [4,2048,1024]

    void *qh_p, *ql_p, *ah_p, *al_p, *wh_p, *wl_p;
    cudaGetSymbolAddress(&qh_p, g_qkvh);
    cudaGetSymbolAddress(&ql_p, g_qkvl);
    cudaGetSymbolAddress(&ah_p, g_ah);
    cudaGetSymbolAddress(&al_p, g_al);
    cudaGetSymbolAddress(&wh_p, g_wh);
    cudaGetSymbolAddress(&wl_p, g_wl);
    __nv_bfloat16 *qkvh = (__nv_bfloat16*)qh_p, *qkvl = (__nv_bfloat16*)ql_p;
    __nv_bfloat16 *ah = (__nv_bfloat16*)ah_p, *al = (__nv_bfloat16*)al_p;
    __nv_bfloat16 *wh = (__nv_bfloat16*)wh_p, *wl = (__nv_bfloat16*)wl_p;

    cudaFuncSetAttribute(gemm_mma<true>,  cudaFuncAttributeMaxDynamicSharedMemorySize, GSMEM);
    cudaFuncSetAttribute(gemm_mma<false>, cudaFuncAttributeMaxDynamicSharedMemorySize, GSMEM);
    cudaFuncSetAttribute(flash_tc, cudaFuncAttributeMaxDynamicSharedMemorySize, FSMEM);

    const int nX = M_TOT * DM, nWq = 3 * DM * DM, nWp = DM * DM;

    // 1) split x, w_qkv; qkv = x @ w_qkv^T -> bf16 hi/lo planes directly
    split_bf16<<<nX / 1024, 256>>>(x, ah, al, nX);
    split_bf16<<<nWq / 1024, 256>>>(w_qkv, wh, wl, nWq);
    gemm_mma<true><<<dim3(3*DM/128, M_TOT/128), 256, GSMEM>>>(
        ah, al, wh, wl, nullptr, qkvh, qkvl, 3*DM, DM);

    // 2) tensor-core flash attention -> att hi/lo planes (into g_ah/g_al)
    flash_tc<<<dim3(TT/128, BB*NH), 256, FSMEM>>>(qkvh, qkvl, ah, al);

    // 3) split w_proj; out = att @ w_proj^T (fp32 out)
    split_bf16<<<nWp / 1024, 256>>>(w_proj, wh, wl, nWp);
    gemm_mma<false><<<dim3(DM/128, M_TOT/128), 256, GSMEM>>>(
        ah, al, wh, wl, out, nullptr, nullptr, DM, DM);
}

// round 8
// speedup vs baseline: 3.9342x; 1.0351x over previous
#include <cuda_runtime.h>
#include <cuda_bf16.h>
#include <math.h>
#include <stdint.h>

#define BB 4
#define TT 2048
#define DM 1024
#define NH 16
#define DH 64
#define M_TOT (BB*TT)   // 8192

// Scratch (allocation-free rule: device globals), all bf16 split planes
__device__ __nv_bfloat16 g_qkvh[(size_t)BB*TT*3*DM];  // qkv hi [B,T,3D]
__device__ __nv_bfloat16 g_qkvl[(size_t)BB*TT*3*DM];  // qkv lo
__device__ __nv_bfloat16 g_ah[(size_t)M_TOT*DM];      // x-split, then att-split (hi)
__device__ __nv_bfloat16 g_al[(size_t)M_TOT*DM];      // (lo)
__device__ __nv_bfloat16 g_wh[(size_t)3*DM*DM];       // weight splits (hi)
__device__ __nv_bfloat16 g_wl[(size_t)3*DM*DM];       // (lo)

// ===========================================================================
// Portable (sm_100 base target) tensor-core primitives. tcgen05 is sm_100a-
// only and this harness compiles at sm_100 — mma.sync/ldmatrix/cp.async only.
// ===========================================================================
__device__ __forceinline__ uint32_t smem_u32(const void* p) {
    uint32_t a;
    asm("{ .reg .u64 t; cvta.to.shared.u64 t, %1; cvt.u32.u64 %0, t; }" : "=r"(a) : "l"(p));
    return a;
}
__device__ __forceinline__ void ldsm4(uint32_t* r, uint32_t addr) {
    asm volatile("ldmatrix.sync.aligned.m8n8.x4.shared.b16 {%0,%1,%2,%3}, [%4];"
        : "=r"(r[0]), "=r"(r[1]), "=r"(r[2]), "=r"(r[3]) : "r"(addr));
}
__device__ __forceinline__ void ldsm4t(uint32_t* r, uint32_t addr) {
    asm volatile("ldmatrix.sync.aligned.m8n8.x4.trans.shared.b16 {%0,%1,%2,%3}, [%4];"
        : "=r"(r[0]), "=r"(r[1]), "=r"(r[2]), "=r"(r[3]) : "r"(addr));
}
__device__ __forceinline__ void ldsm2(uint32_t* r, uint32_t addr) {
    asm volatile("ldmatrix.sync.aligned.m8n8.x2.shared.b16 {%0,%1}, [%2];"
        : "=r"(r[0]), "=r"(r[1]) : "r"(addr));
}
__device__ __forceinline__ void mma_bf16(float* d, const uint32_t* a, const uint32_t* b) {
    asm volatile("mma.sync.aligned.m16n8k16.row.col.f32.bf16.bf16.f32 "
        "{%0,%1,%2,%3}, {%4,%5,%6,%7}, {%8,%9}, {%0,%1,%2,%3};"
        : "+f"(d[0]), "+f"(d[1]), "+f"(d[2]), "+f"(d[3])
        : "r"(a[0]), "r"(a[1]), "r"(a[2]), "r"(a[3]), "r"(b[0]), "r"(b[1]));
}
#define CP_ASYNC16(s, g) \
    asm volatile("cp.async.cg.shared.global [%0], [%1], 16;" :: "r"(s), "l"(g))
#define CP_COMMIT() asm volatile("cp.async.commit_group;" ::: "memory")
template <int N> __device__ __forceinline__ void cp_wait() {
    asm volatile("cp.async.wait_group %0;" :: "n"(N) : "memory");
}
__device__ __forceinline__ float ex2(float x) {
    float y;
    asm("ex2.approx.ftz.f32 %0, %1;" : "=f"(y) : "f"(x));
    return y;
}
__device__ __forceinline__ void splitpack(float a, float b, uint32_t& hi, uint32_t& lo) {
    __nv_bfloat16 ha = __float2bfloat16(a), hb = __float2bfloat16(b);
    __nv_bfloat16 la = __float2bfloat16(a - __bfloat162float(ha));
    __nv_bfloat16 lb = __float2bfloat16(b - __bfloat162float(hb));
    hi = (uint32_t)__bfloat16_as_ushort(ha) | ((uint32_t)__bfloat16_as_ushort(hb) << 16);
    lo = (uint32_t)__bfloat16_as_ushort(la) | ((uint32_t)__bfloat16_as_ushort(lb) << 16);
}

// ===========================================================================
// fp32 -> bf16 (hi, lo) split pass:  v = hi + lo + O(2^-17 |v|)
// ===========================================================================
__global__ __launch_bounds__(256) void split_bf16(
    const float* __restrict__ src, __nv_bfloat16* __restrict__ hi,
    __nv_bfloat16* __restrict__ lo, int n)
{
    int i = (blockIdx.x * 256 + threadIdx.x) * 4;
    if (i >= n) return;
    float4 v = *(const float4*)(src + i);
    uint2 hp, lp;
    splitpack(v.x, v.y, hp.x, lp.x);
    splitpack(v.z, v.w, hp.y, lp.y);
    *(uint2*)(hi + i) = hp;
    *(uint2*)(lo + i) = lp;
}

// ===========================================================================
// HMMA bf16-split GEMM (NT): C = A * B^T, fp32 accumulate.
// CTA 128x128, 8 warps (2x4), warp tile 64x32, BK=32, double-buffered cp.async.
// Rows: 32 halves = 64 B data padded to 80 B (ldmatrix conflict-free).
// SPLIT=true: write bf16 hi/lo planes (Ch/Cl).  SPLIT=false: write fp32 C.
// ===========================================================================
#define BK 32
#define ABYTES (128*80)
#define STG    (4*ABYTES)
#define GSMEM  (2*STG)               // 81920 B

template <bool SPLIT>
__global__ __launch_bounds__(256, 1) void gemm_mma(
    const __nv_bfloat16* __restrict__ Ah, const __nv_bfloat16* __restrict__ Al,
    const __nv_bfloat16* __restrict__ Bh, const __nv_bfloat16* __restrict__ Bl,
    float* __restrict__ C, __nv_bfloat16* __restrict__ Ch, __nv_bfloat16* __restrict__ Cl,
    int N, int K)
{
    extern __shared__ char smem[];
    const uint32_t sb = smem_u32(smem);
    const int tid = threadIdx.x, lane = tid & 31, wid = tid >> 5;
    const int wm = wid >> 2, wn = wid & 3;
    const int mBlk = blockIdx.y * 128, nBlk = blockIdx.x * 128;

    float acc[4][4][4];
#pragma unroll
    for (int mt = 0; mt < 4; mt++)
#pragma unroll
        for (int nt = 0; nt < 4; nt++)
#pragma unroll
            for (int j = 0; j < 4; j++) acc[mt][nt][j] = 0.f;

    const int NCH = K / BK;

    auto load_stage = [&](int s, int k0) {
        uint32_t so = sb + (s ? STG : 0);
#pragma unroll
        for (int i = tid; i < 512; i += 256) {
            int r = i >> 2, ch = i & 3;
            uint32_t d = so + (uint32_t)r * 80 + ch * 16;
            size_t goA = (size_t)(mBlk + r) * K + k0 + ch * 8;
            size_t goB = (size_t)(nBlk + r) * K + k0 + ch * 8;
            CP_ASYNC16(d,            Ah + goA);
            CP_ASYNC16(d + ABYTES,   Al + goA);
            CP_ASYNC16(d + 2*ABYTES, Bh + goB);
            CP_ASYNC16(d + 3*ABYTES, Bl + goB);
        }
        CP_COMMIT();
    };

    load_stage(0, 0);

    for (int c = 0; c < NCH; c++) {
        if (c + 1 < NCH) { load_stage((c + 1) & 1, (c + 1) * BK); cp_wait<1>(); }
        else             { cp_wait<0>(); }
        __syncthreads();

        uint32_t so = sb + ((c & 1) ? STG : 0);
        const uint32_t aRow = wm * 64 + (lane & 15);
        const uint32_t bRow = wn * 32 + (lane & 7);
#pragma unroll
        for (int ks = 0; ks < 2; ks++) {
            const uint32_t ak = ks * 16 + (lane >> 4) * 8;
            const uint32_t bk = ks * 16 + ((lane >> 3) & 1) * 8;
            uint32_t ah[4][4], al[4][4];
#pragma unroll
            for (int mt = 0; mt < 4; mt++) {
                uint32_t addr = so + (aRow + mt * 16) * 80 + ak * 2;
                ldsm4(ah[mt], addr);
                ldsm4(al[mt], addr + ABYTES);
            }
#pragma unroll
            for (int nt = 0; nt < 4; nt++) {
                uint32_t baddr = so + 2*ABYTES + (bRow + nt * 8) * 80 + bk * 2;
                uint32_t bh[2], bl[2];
                ldsm2(bh, baddr);
                ldsm2(bl, baddr + ABYTES);
#pragma unroll
                for (int mt = 0; mt < 4; mt++) {
                    mma_bf16(acc[mt][nt], ah[mt], bh);
                    mma_bf16(acc[mt][nt], ah[mt], bl);
                    mma_bf16(acc[mt][nt], al[mt], bh);
                }
            }
        }
        __syncthreads();
    }

    const int row0 = mBlk + wm * 64, col0 = nBlk + wn * 32;
#pragma unroll
    for (int mt = 0; mt < 4; mt++) {
        int r = row0 + mt * 16 + (lane >> 2);
#pragma unroll
        for (int nt = 0; nt < 4; nt++) {
            int cc = col0 + nt * 8 + (lane & 3) * 2;
            if (SPLIT) {
                uint32_t h0, l0, h1, l1;
                splitpack(acc[mt][nt][0], acc[mt][nt][1], h0, l0);
                splitpack(acc[mt][nt][2], acc[mt][nt][3], h1, l1);
                *(uint32_t*)(Ch + (size_t)r * N + cc)       = h0;
                *(uint32_t*)(Cl + (size_t)r * N + cc)       = l0;
                *(uint32_t*)(Ch + (size_t)(r + 8) * N + cc) = h1;
                *(uint32_t*)(Cl + (size_t)(r + 8) * N + cc) = l1;
            } else {
                *(float2*)(C + (size_t)r * N + cc)       = make_float2(acc[mt][nt][0], acc[mt][nt][1]);
                *(float2*)(C + (size_t)(r + 8) * N + cc) = make_float2(acc[mt][nt][2], acc[mt][nt][3]);
            }
        }
    }
}

// ===========================================================================
// Tensor-core flash attention (FA2-style), bf16-split, fp32 accum.
// Grid (T/128, B*H), 256 threads (8 warps, 16 q-rows each). KEY TILE = 32
// (shrinks live regs: s[4][4] + aph/apl[2][4]) so 2 CTAs/SM fit (reg-bound
// at tile=64: 150 regs -> 1 CTA).  __launch_bounds__(256, 2).
// Rows: 64 halves = 128 B data padded to 144 B (ldmatrix conflict-free).
// smem: Qh Ql (128x144) | 2 stages x {Kh,Kl,Vh,Vl} (32x144 each) = 73728 B.
// ===========================================================================
#define FROW 144
#define QPL  (128*FROW)       // 18432 per Q plane
#define KVPL (32*FROW)        // 4608 per K/V plane
#define SQH 0
#define SQL QPL
#define SKV (2*QPL)           // 36864
#define KVSTG (4*KVPL)        // 18432 per stage
#define FSMEM (SKV + 2*KVSTG) // 73728

__global__ __launch_bounds__(256, 2) void flash_tc(
    const __nv_bfloat16* __restrict__ Ph, const __nv_bfloat16* __restrict__ Pl,
    __nv_bfloat16* __restrict__ Oh, __nv_bfloat16* __restrict__ Ol)
{
    extern __shared__ char smem[];
    const uint32_t sb = smem_u32(smem);
    const int tid = threadIdx.x, lane = tid & 31, wid = tid >> 5;
    const int qt = blockIdx.x, bh = blockIdx.y;
    const int b = bh >> 4, h = bh & 15;
    const size_t rowbase = (size_t)b * TT;
    const int q0 = qt * 128;
    const int hoff = h * DH;

    // ---- Q tile (hi/lo), 128 rows x 64 halves, cp.async
#pragma unroll
    for (int i = tid; i < 2048; i += 256) {
        int pl = i >> 10, r = (i >> 3) & 127, ch = i & 7;
        const __nv_bfloat16* src = (pl ? Pl : Ph) + (rowbase + q0 + r) * 3*DM + hoff + ch * 8;
        CP_ASYNC16(sb + (pl ? SQL : SQH) + r * FROW + ch * 16, src);
    }
    auto load_kv = [&](int s, int kt) {
        uint32_t so = sb + SKV + s * KVSTG;
#pragma unroll
        for (int i = tid; i < 1024; i += 256) {
            int p = i >> 8, r = (i >> 3) & 31, ch = i & 7;
            const __nv_bfloat16* basep = (p & 1) ? Pl : Ph;
            int sec = (p >> 1) ? 2*DM : DM;
            const __nv_bfloat16* src = basep + (rowbase + kt*32 + r) * 3*DM + sec + hoff + ch * 8;
            CP_ASYNC16(so + p * KVPL + r * FROW + ch * 16, src);
        }
    };
    load_kv(0, 0);
    CP_COMMIT();

    const int wq = wid * 16;
    const float CSC = 0.125f * 1.4426950408889634f;   // scale * log2(e)
    float o[8][4];
#pragma unroll
    for (int j = 0; j < 8; j++)
#pragma unroll
        for (int i = 0; i < 4; i++) o[j][i] = 0.f;
    float m0 = -1e30f, m1 = -1e30f, l0 = 0.f, l1 = 0.f;

    for (int kt = 0; kt < TT/32; kt++) {
        if (kt + 1 < TT/32) { load_kv((kt + 1) & 1, kt + 1); CP_COMMIT(); cp_wait<1>(); }
        else                { cp_wait<0>(); }
        __syncthreads();
        const uint32_t kvb = sb + SKV + (kt & 1) * KVSTG;

        // ---- S = Q K^T  (split: QhKh + QhKl + QlKh), 16q x 32k per warp
        float s[4][4];
#pragma unroll
        for (int j = 0; j < 4; j++)
#pragma unroll
            for (int i = 0; i < 4; i++) s[j][i] = 0.f;
#pragma unroll
        for (int ks = 0; ks < 4; ks++) {
            uint32_t qaddr = sb + SQH + (wq + (lane & 15)) * FROW + (ks*16 + (lane >> 4)*8) * 2;
            uint32_t qh[4], ql[4];
            ldsm4(qh, qaddr);
            ldsm4(ql, qaddr + SQL);
#pragma unroll
            for (int np = 0; np < 2; np++) {
                uint32_t kaddr = kvb + (np*16 + (lane & 15)) * FROW + (ks*16 + (lane >> 4)*8) * 2;
                uint32_t kh[4], kl[4];
                ldsm4(kh, kaddr);
                ldsm4(kl, kaddr + KVPL);
                uint32_t b0h[2] = {kh[0], kh[2]}, b1h[2] = {kh[1], kh[3]};
                uint32_t b0l[2] = {kl[0], kl[2]}, b1l[2] = {kl[1], kl[3]};
                mma_bf16(s[2*np],   qh, b0h);
                mma_bf16(s[2*np],   qh, b0l);
                mma_bf16(s[2*np],   ql, b0h);
                mma_bf16(s[2*np+1], qh, b1h);
                mma_bf16(s[2*np+1], qh, b1l);
                mma_bf16(s[2*np+1], ql, b1h);
            }
        }

        // ---- online softmax (log2 domain, scale folded in)
#pragma unroll
        for (int j = 0; j < 4; j++)
#pragma unroll
            for (int i = 0; i < 4; i++) s[j][i] *= CSC;
        float t0 = -1e30f, t1 = -1e30f;
#pragma unroll
        for (int j = 0; j < 4; j++) {
            t0 = fmaxf(t0, fmaxf(s[j][0], s[j][1]));
            t1 = fmaxf(t1, fmaxf(s[j][2], s[j][3]));
        }
        t0 = fmaxf(t0, __shfl_xor_sync(0xffffffffu, t0, 1));
        t0 = fmaxf(t0, __shfl_xor_sync(0xffffffffu, t0, 2));
        t1 = fmaxf(t1, __shfl_xor_sync(0xffffffffu, t1, 1));
        t1 = fmaxf(t1, __shfl_xor_sync(0xffffffffu, t1, 2));
        float m0n = fmaxf(m0, t0), m1n = fmaxf(m1, t1);
        float r0 = ex2(m0 - m0n), r1 = ex2(m1 - m1n);
        m0 = m0n; m1 = m1n;

        float ls0 = 0.f, ls1 = 0.f;
        uint32_t aph[2][4], apl[2][4];
#pragma unroll
        for (int j = 0; j < 4; j++) {
            float p0 = ex2(s[j][0] - m0), p1 = ex2(s[j][1] - m0);
            float p2 = ex2(s[j][2] - m1), p3 = ex2(s[j][3] - m1);
            ls0 += p0 + p1; ls1 += p2 + p3;
            int jj = j >> 1, rb = (j & 1) * 2;
            splitpack(p0, p1, aph[jj][rb],     apl[jj][rb]);
            splitpack(p2, p3, aph[jj][rb + 1], apl[jj][rb + 1]);
        }
        ls0 += __shfl_xor_sync(0xffffffffu, ls0, 1);
        ls0 += __shfl_xor_sync(0xffffffffu, ls0, 2);
        ls1 += __shfl_xor_sync(0xffffffffu, ls1, 1);
        ls1 += __shfl_xor_sync(0xffffffffu, ls1, 2);
        l0 = l0 * r0 + ls0;
        l1 = l1 * r1 + ls1;
#pragma unroll
        for (int j = 0; j < 8; j++) {
            o[j][0] *= r0; o[j][1] *= r0; o[j][2] *= r1; o[j][3] *= r1;
        }

        // ---- O += P V  (split: PhVh + PhVl + PlVh), V via ldmatrix.trans
#pragma unroll
        for (int jj = 0; jj < 2; jj++) {
#pragma unroll
            for (int np = 0; np < 4; np++) {
                uint32_t vaddr = kvb + 2*KVPL + (jj*16 + (lane & 15)) * FROW + (np*16 + (lane >> 4)*8) * 2;
                uint32_t vh[4], vl[4];
                ldsm4t(vh, vaddr);
                ldsm4t(vl, vaddr + KVPL);
                uint32_t bh0[2] = {vh[0], vh[1]}, bh1[2] = {vh[2], vh[3]};
                uint32_t bl0[2] = {vl[0], vl[1]}, bl1[2] = {vl[2], vl[3]};
                mma_bf16(o[2*np],   aph[jj], bh0);
                mma_bf16(o[2*np],   aph[jj], bl0);
                mma_bf16(o[2*np],   apl[jj], bh0);
                mma_bf16(o[2*np+1], aph[jj], bh1);
                mma_bf16(o[2*np+1], aph[jj], bl1);
                mma_bf16(o[2*np+1], apl[jj], bh1);
            }
        }
        __syncthreads();
    }

    // ---- epilogue: normalize, split, write att hi/lo planes [B,T,D]
    float inv0 = 1.f / l0, inv1 = 1.f / l1;
    const size_t rA = rowbase + q0 + wq + (lane >> 2);
    const size_t rB = rA + 8;
#pragma unroll
    for (int j = 0; j < 8; j++) {
        int col = hoff + j * 8 + (lane & 3) * 2;
        uint32_t h0, lo0, h1, lo1;
        splitpack(o[j][0] * inv0, o[j][1] * inv0, h0, lo0);
        splitpack(o[j][2] * inv1, o[j][3] * inv1, h1, lo1);
        *(uint32_t*)(Oh + rA * DM + col) = h0;
        *(uint32_t*)(Ol + rA * DM + col) = lo0;
        *(uint32_t*)(Oh + rB * DM + col) = h1;
        *(uint32_t*)(Ol + rB * DM + col) = lo1;
    }
}

// ---------------------------------------------------------------------------
extern "C" void kernel_launch(void* const* d_in, const int* in_sizes, int n_in,
                              void* d_out, int out_size)
{
    const float* x      = (const float*)d_in[0];  // [4,2048,1024]
    const float* w_qkv  = (const float*)d_in[1];  // [3072,1024]
    const float* w_proj = (const float*)d_in[2];  // [1024,1024]
    float* out = (float*)d_out;                   // [4,2048,1024]

    void *qh_p, *ql_p, *ah_p, *al_p, *wh_p, *wl_p;
    cudaGetSymbolAddress(&qh_p, g_qkvh);
    cudaGetSymbolAddress(&ql_p, g_qkvl);
    cudaGetSymbolAddress(&ah_p, g_ah);
    cudaGetSymbolAddress(&al_p, g_al);
    cudaGetSymbolAddress(&wh_p, g_wh);
    cudaGetSymbolAddress(&wl_p, g_wl);
    __nv_bfloat16 *qkvh = (__nv_bfloat16*)qh_p, *qkvl = (__nv_bfloat16*)ql_p;
    __nv_bfloat16 *ah = (__nv_bfloat16*)ah_p, *al = (__nv_bfloat16*)al_p;
    __nv_bfloat16 *wh = (__nv_bfloat16*)wh_p, *wl = (__nv_bfloat16*)wl_p;

    cudaFuncSetAttribute(gemm_mma<true>,  cudaFuncAttributeMaxDynamicSharedMemorySize, GSMEM);
    cudaFuncSetAttribute(gemm_mma<false>, cudaFuncAttributeMaxDynamicSharedMemorySize, GSMEM);
    cudaFuncSetAttribute(flash_tc, cudaFuncAttributeMaxDynamicSharedMemorySize, FSMEM);

    const int nX = M_TOT * DM, nWq = 3 * DM * DM, nWp = DM * DM;

    // 1) split x, w_qkv; qkv = x @ w_qkv^T -> bf16 hi/lo planes directly
    split_bf16<<<nX / 1024, 256>>>(x, ah, al, nX);
    split_bf16<<<nWq / 1024, 256>>>(w_qkv, wh, wl, nWq);
    gemm_mma<true><<<dim3(3*DM/128, M_TOT/128), 256, GSMEM>>>(
        ah, al, wh, wl, nullptr, qkvh, qkvl, 3*DM, DM);

    // 2) tensor-core flash attention -> att hi/lo planes (into g_ah/g_al)
    flash_tc<<<dim3(TT/128, BB*NH), 256, FSMEM>>>(qkvh, qkvl, ah, al);

    // 3) split w_proj; out = att @ w_proj^T (fp32 out)
    split_bf16<<<nWp / 1024, 256>>>(w_proj, wh, wl, nWp);
    gemm_mma<false><<<dim3(DM/128, M_TOT/128), 256, GSMEM>>>(
        ah, al, wh, wl, out, nullptr, nullptr, DM, DM);
}